// round 7
// baseline (speedup 1.0000x reference)
#include <cuda_runtime.h>
#include <math.h>

#define H 1024
#define L 128
#define V 50257
#define NB 296
#define NT 256
#define NWARPS (NB * 8)

// ---- scratch (device globals; no allocation allowed) ----
__device__ __align__(16) float g_attn_logits[L];
__device__ __align__(16) float g_with_attn[H];
__device__ __align__(16) float g_rnn_in[H];
__device__ __align__(16) float g_gh[3 * H];      // W_hh @ h0 + b_hh (hoisted)
__device__ __align__(16) float g_hnew[H];
__device__ __align__(16) float g_logits[V];
__device__ float g_sumexp;
__device__ unsigned int g_cnt[5];
__device__ volatile unsigned int g_flag[5];

__device__ __forceinline__ float warp_sum(float v) {
#pragma unroll
    for (int o = 16; o > 0; o >>= 1) v += __shfl_xor_sync(0xffffffffu, v, o);
    return v;
}

__device__ __forceinline__ float dot4(float4 a, float4 b) {
    return a.x * b.x + a.y * b.y + a.z * b.z + a.w * b.w;
}

__global__ void __launch_bounds__(NT, 2) k_fused(
    const int* __restrict__ x,
    const float* __restrict__ hidden,
    const float* __restrict__ enc,
    const float* __restrict__ emb,
    const float* __restrict__ attn_W,
    const float* __restrict__ attn_b,
    const float* __restrict__ comb_W,
    const float* __restrict__ comb_b,
    const float* __restrict__ W_ih,
    const float* __restrict__ W_hh,
    const float* __restrict__ b_ih,
    const float* __restrict__ b_hh,
    const float* __restrict__ out_W,
    const float* __restrict__ out_b,
    float* __restrict__ out)   // [logp V][h_new H][attn_w L]
{
    __shared__ unsigned int sense[5];
    __shared__ float sw[L];
    __shared__ float redm[4], reds[4];
    __shared__ float sg[8][4];
    __shared__ float s_se[8];

    int t = threadIdx.x;
    int b = blockIdx.x;
    int w = t >> 5;
    int lane = t & 31;
    int gw = b * 8 + w;

    if (t < 5) sense[t] = g_flag[t];
    __syncthreads();

    // sense-reversing grid barrier
    auto gbar = [&](int i) {
        __syncthreads();
        if (t == 0) {
            __threadfence();
            unsigned int old = atomicAdd(&g_cnt[i], 1u);
            if (old == NB - 1) {
                g_cnt[i] = 0u;
                __threadfence();
                g_flag[i] = sense[i] ^ 1u;
            } else {
                while (g_flag[i] == sense[i]) { }
            }
            __threadfence();
        }
        __syncthreads();
    };

    const float* erow = emb + (long long)x[0] * H;

    // ===== P0: attn logits (tasks 0..127) + gh rows (tasks 128..3199) + init =====
    if (b == 0) {
        *(float4*)(g_with_attn + t * 4) = make_float4(0.f, 0.f, 0.f, 0.f);
        if (t == 0) g_sumexp = 0.f;
    }
    for (int task = gw; task < 3200; task += NWARPS) {
        if (task < 128) {
            const float* wrow = attn_W + (long long)task * 2 * H;
            float4 a[8];
            float acc = 0.f;
#pragma unroll
            for (int k = 0; k < 8; k++) a[k] = __ldcs((const float4*)(wrow + k * 128 + lane * 4));
#pragma unroll
            for (int k = 0; k < 8; k++) acc += dot4(a[k], *(const float4*)(erow + k * 128 + lane * 4));
#pragma unroll
            for (int k = 0; k < 8; k++) a[k] = __ldcs((const float4*)(wrow + H + k * 128 + lane * 4));
#pragma unroll
            for (int k = 0; k < 8; k++) acc += dot4(a[k], *(const float4*)(hidden + k * 128 + lane * 4));
            acc = warp_sum(acc);
            if (lane == 0) g_attn_logits[task] = acc + attn_b[task];
        } else {
            int r = task - 128;      // 0..3071
            const float* wrow = W_hh + (long long)r * H;
            float4 a[8];
#pragma unroll
            for (int k = 0; k < 8; k++) a[k] = __ldcs((const float4*)(wrow + k * 128 + lane * 4));
            float acc = 0.f;
#pragma unroll
            for (int k = 0; k < 8; k++) acc += dot4(a[k], *(const float4*)(hidden + k * 128 + lane * 4));
            acc = warp_sum(acc);
            if (lane == 0) g_gh[r] = acc + b_hh[r];
        }
    }
    gbar(0);

    // ===== P1: softmax (recomputed per participating block) + with_attention =====
    if (b < 128) {
        float v = 0.f;
        if (t < L) {
            v = g_attn_logits[t];
            float m = v;
#pragma unroll
            for (int o = 16; o > 0; o >>= 1) m = fmaxf(m, __shfl_xor_sync(0xffffffffu, m, o));
            if (lane == 0) redm[t >> 5] = m;
        }
        __syncthreads();
        float m4 = fmaxf(fmaxf(redm[0], redm[1]), fmaxf(redm[2], redm[3]));
        if (t < L) {
            float e = expf(v - m4);
            float ss = warp_sum(e);
            if (lane == 0) reds[t >> 5] = ss;
            sw[t] = e;
        }
        __syncthreads();
        float tot = (reds[0] + reds[1]) + (reds[2] + reds[3]);
        if (t < L) {
            sw[t] = sw[t] / tot;
            if (b == 0) out[V + H + t] = sw[t];
        }
        __syncthreads();
        int cc = b & 3;            // 4 col chunks of 256
        int rc = b >> 2;           // 32 row chunks of 4
        int col = cc * 256 + t;
        int l0 = rc * 4;
        float acc = 0.f;
#pragma unroll
        for (int j = 0; j < 4; j++) acc += sw[l0 + j] * __ldg(enc + (l0 + j) * H + col);
        atomicAdd(&g_with_attn[col], acc);
    }
    gbar(1);

    // ===== P2: rnn_in[i] = relu(comb_W[i] . [emb, with_attn] + comb_b[i]) =====
    if (gw < H) {
        const float* wrow = comb_W + (long long)gw * 2 * H;
        float4 a[8];
        float acc = 0.f;
#pragma unroll
        for (int k = 0; k < 8; k++) a[k] = __ldcs((const float4*)(wrow + k * 128 + lane * 4));
#pragma unroll
        for (int k = 0; k < 8; k++) acc += dot4(a[k], *(const float4*)(erow + k * 128 + lane * 4));
#pragma unroll
        for (int k = 0; k < 8; k++) a[k] = __ldcs((const float4*)(wrow + H + k * 128 + lane * 4));
#pragma unroll
        for (int k = 0; k < 8; k++) acc += dot4(a[k], *(const float4*)(g_with_attn + k * 128 + lane * 4));
        acc = warp_sum(acc);
        if (lane == 0) g_rnn_in[gw] = fmaxf(acc + comb_b[gw], 0.f);
    }
    gbar(2);

    // ===== P3: GRU. 2 warps per output i (each a 512-half of all 3 gates) =====
    if (gw < 2 * H) {
        int i = gw >> 1;
        int half = gw & 1;
        int base = half * 512;
        float4 bv[4];
#pragma unroll
        for (int k = 0; k < 4; k++) bv[k] = *(const float4*)(g_rnn_in + base + k * 128 + lane * 4);
        float4 a[12];
#pragma unroll
        for (int g = 0; g < 3; g++)
#pragma unroll
            for (int k = 0; k < 4; k++)
                a[g * 4 + k] = __ldcs((const float4*)(W_ih + (long long)(g * H + i) * H + base + k * 128 + lane * 4));
        float a0 = 0.f, a1 = 0.f, a2 = 0.f;
#pragma unroll
        for (int k = 0; k < 4; k++) {
            a0 += dot4(a[k], bv[k]);
            a1 += dot4(a[4 + k], bv[k]);
            a2 += dot4(a[8 + k], bv[k]);
        }
        a0 = warp_sum(a0);
        a1 = warp_sum(a1);
        a2 = warp_sum(a2);
        if (lane == 0) { sg[w][0] = a0; sg[w][1] = a1; sg[w][2] = a2; }
    }
    __syncthreads();
    if (gw < 2 * H && (w & 1) == 0 && lane == 0) {
        int i = gw >> 1;
        float gx_r = sg[w][0] + sg[w + 1][0] + b_ih[i];
        float gx_z = sg[w][1] + sg[w + 1][1] + b_ih[H + i];
        float gx_n = sg[w][2] + sg[w + 1][2] + b_ih[2 * H + i];
        float r = 1.f / (1.f + expf(-(gx_r + g_gh[i])));
        float z = 1.f / (1.f + expf(-(gx_z + g_gh[H + i])));
        float n = tanhf(gx_n + r * g_gh[2 * H + i]);
        float h = (1.f - z) * n + z * hidden[i];
        g_hnew[i] = h;
        out[V + i] = h;
    }
    gbar(3);

    // ===== P5: vocab GEMV (2 rows/warp, grid-stride) + fused sum-exp =====
    {
        float4 hreg[8];
#pragma unroll
        for (int k = 0; k < 8; k++)
            hreg[k] = *(const float4*)(g_hnew + k * 128 + lane * 4);
        float se = 0.f;
        for (int v0 = gw * 2; v0 < V; v0 += 2 * NWARPS) {
            bool has1 = (v0 + 1 < V);
            const float* row0 = out_W + (long long)v0 * H + lane * 4;
            float4 a0[8], a1[8];
#pragma unroll
            for (int k = 0; k < 8; k++) a0[k] = __ldcs((const float4*)(row0 + k * 128));
            if (has1) {
#pragma unroll
                for (int k = 0; k < 8; k++) a1[k] = __ldcs((const float4*)(row0 + H + k * 128));
            }
            float acc0 = 0.f, acc1 = 0.f;
#pragma unroll
            for (int k = 0; k < 8; k++) {
                acc0 += dot4(a0[k], hreg[k]);
                if (has1) acc1 += dot4(a1[k], hreg[k]);
            }
            acc0 = warp_sum(acc0);
            acc1 = warp_sum(acc1);
            if (lane == 0) {
                float lg0 = acc0 + out_b[v0];
                g_logits[v0] = lg0;
                se += expf(lg0);
                if (has1) {
                    float lg1 = acc1 + out_b[v0 + 1];
                    g_logits[v0 + 1] = lg1;
                    se += expf(lg1);
                }
            }
        }
        if (lane == 0) s_se[w] = se;
    }
    __syncthreads();
    if (t == 0) {
        float tot = 0.f;
#pragma unroll
        for (int k = 0; k < 8; k++) tot += s_se[k];
        atomicAdd(&g_sumexp, tot);
    }
    gbar(4);

    // ===== P6: logp[v] = logit[v] - log(sum exp) =====
    {
        float lse = logf(g_sumexp);
        for (int v = b * NT + t; v < V; v += NB * NT)
            out[v] = g_logits[v] - lse;
    }
}

extern "C" void kernel_launch(void* const* d_in, const int* in_sizes, int n_in,
                              void* d_out, int out_size) {
    const int*   x       = (const int*)d_in[0];
    const float* hidden  = (const float*)d_in[1];
    const float* enc     = (const float*)d_in[2];
    const float* emb     = (const float*)d_in[3];
    const float* attn_W  = (const float*)d_in[4];
    const float* attn_b  = (const float*)d_in[5];
    const float* comb_W  = (const float*)d_in[6];
    const float* comb_b  = (const float*)d_in[7];
    const float* W_ih    = (const float*)d_in[8];
    const float* W_hh    = (const float*)d_in[9];
    const float* b_ih    = (const float*)d_in[10];
    const float* b_hh    = (const float*)d_in[11];
    const float* out_W   = (const float*)d_in[12];
    const float* out_b   = (const float*)d_in[13];
    float* out = (float*)d_out;   // layout: [logp V][h_new H][attn_w L]

    k_fused<<<NB, NT>>>(x, hidden, enc, emb, attn_W, attn_b, comb_W, comb_b,
                        W_ih, W_hh, b_ih, b_hh, out_W, out_b, out);
}

// round 8
// speedup vs baseline: 1.1184x; 1.1184x over previous
#include <cuda_runtime.h>
#include <math.h>

#define H 1024
#define L 128
#define V 50257
#define FNB 444              // 3 blocks/SM * 148 SMs — all co-resident
#define FNT 256
#define FNW (FNB * 8)

// ---- scratch (device globals; no allocation allowed) ----
__device__ __align__(16) float g_attn_logits[L];
__device__ __align__(16) float g_with_attn[H];
__device__ __align__(16) float g_rnn_in[H];
__device__ __align__(16) float g_gh[3 * H];      // W_hh @ h0 + b_hh (hoisted)
__device__ __align__(16) float g_hnew[H];
__device__ __align__(16) float g_logits[V];
__device__ unsigned int g_max_enc;   // ordered-uint encoded max
__device__ float g_sumexp;
__device__ unsigned int g_cnt[3];
__device__ volatile unsigned int g_flag[3];

__device__ __forceinline__ float warp_sum(float v) {
#pragma unroll
    for (int o = 16; o > 0; o >>= 1) v += __shfl_xor_sync(0xffffffffu, v, o);
    return v;
}

__device__ __forceinline__ float dot4(float4 a, float4 b) {
    return a.x * b.x + a.y * b.y + a.z * b.z + a.w * b.w;
}

// encode float so unsigned compare == float compare
__device__ __forceinline__ unsigned int enc_f(float f) {
    unsigned int u = __float_as_uint(f);
    return (u & 0x80000000u) ? ~u : (u | 0x80000000u);
}
__device__ __forceinline__ float dec_f(unsigned int u) {
    return (u & 0x80000000u) ? __uint_as_float(u ^ 0x80000000u)
                             : __uint_as_float(~u);
}

// ===== K1: fused front (attn logits + gh, softmax+with_attn, rnn_in, GRU) =====
__global__ void __launch_bounds__(FNT, 3) k_front(
    const int* __restrict__ x,
    const float* __restrict__ hidden,
    const float* __restrict__ enc,
    const float* __restrict__ emb,
    const float* __restrict__ attn_W,
    const float* __restrict__ attn_b,
    const float* __restrict__ comb_W,
    const float* __restrict__ comb_b,
    const float* __restrict__ W_ih,
    const float* __restrict__ W_hh,
    const float* __restrict__ b_ih,
    const float* __restrict__ b_hh,
    float* __restrict__ out)
{
    __shared__ unsigned int sense[3];
    __shared__ float sw[L];
    __shared__ float redm[4], reds[4];

    int t = threadIdx.x;
    int b = blockIdx.x;
    int w = t >> 5;
    int lane = t & 31;
    int gw = b * 8 + w;

    if (t < 3) sense[t] = g_flag[t];
    __syncthreads();

    auto gbar = [&](int i) {
        __syncthreads();
        if (t == 0) {
            __threadfence();
            unsigned int old = atomicAdd(&g_cnt[i], 1u);
            if (old == FNB - 1) {
                g_cnt[i] = 0u;
                __threadfence();
                g_flag[i] = sense[i] ^ 1u;
            } else {
                while (g_flag[i] == sense[i]) { }
            }
            __threadfence();
        }
        __syncthreads();
    };

    const float* erow = emb + (long long)x[0] * H;

    // ---- P0: attn logits (tasks 0..127) + gh (tasks 128..3199) + init ----
    if (b == FNB - 1) {
        *(float4*)(g_with_attn + t * 4) = make_float4(0.f, 0.f, 0.f, 0.f);
        if (t == 0) { g_max_enc = 0u; g_sumexp = 0.f; }
    }
    if (gw < 3200) {
        if (gw < 128) {
            const float* wrow = attn_W + (long long)gw * 2 * H;
            float4 a[8];
            float acc = 0.f;
#pragma unroll
            for (int k = 0; k < 8; k++) a[k] = __ldcs((const float4*)(wrow + k * 128 + lane * 4));
#pragma unroll
            for (int k = 0; k < 8; k++) acc += dot4(a[k], *(const float4*)(erow + k * 128 + lane * 4));
#pragma unroll
            for (int k = 0; k < 8; k++) a[k] = __ldcs((const float4*)(wrow + H + k * 128 + lane * 4));
#pragma unroll
            for (int k = 0; k < 8; k++) acc += dot4(a[k], *(const float4*)(hidden + k * 128 + lane * 4));
            acc = warp_sum(acc);
            if (lane == 0) g_attn_logits[gw] = acc + attn_b[gw];
        } else {
            int r = gw - 128;      // 0..3071
            const float* wrow = W_hh + (long long)r * H;
            float4 a[8];
#pragma unroll
            for (int k = 0; k < 8; k++) a[k] = __ldcs((const float4*)(wrow + k * 128 + lane * 4));
            float acc = 0.f;
#pragma unroll
            for (int k = 0; k < 8; k++) acc += dot4(a[k], *(const float4*)(hidden + k * 128 + lane * 4));
            acc = warp_sum(acc);
            if (lane == 0) g_gh[r] = acc + b_hh[r];
        }
    }
    gbar(0);

    // ---- P1: softmax (recomputed per block) + with_attention ----
    if (b < 128) {
        float v = 0.f;
        if (t < L) {
            v = g_attn_logits[t];
            float m = v;
#pragma unroll
            for (int o = 16; o > 0; o >>= 1) m = fmaxf(m, __shfl_xor_sync(0xffffffffu, m, o));
            if (lane == 0) redm[t >> 5] = m;
        }
        __syncthreads();
        float m4 = fmaxf(fmaxf(redm[0], redm[1]), fmaxf(redm[2], redm[3]));
        if (t < L) {
            float e = expf(v - m4);
            float ss = warp_sum(e);
            if (lane == 0) reds[t >> 5] = ss;
            sw[t] = e;
        }
        __syncthreads();
        float tot = (reds[0] + reds[1]) + (reds[2] + reds[3]);
        if (t < L) {
            sw[t] = sw[t] / tot;
            if (b == 0) out[V + H + t] = sw[t];
        }
        __syncthreads();
        int col = (b & 3) * 256 + t;   // 4 col chunks
        int l0 = (b >> 2) * 4;         // 32 row chunks of 4
        float acc = 0.f;
#pragma unroll
        for (int j = 0; j < 4; j++) acc += sw[l0 + j] * __ldg(enc + (l0 + j) * H + col);
        atomicAdd(&g_with_attn[col], acc);
    }
    gbar(1);

    // ---- P2: rnn_in[i] = relu(comb_W[i] . [emb, with_attn] + comb_b[i]) ----
    if (gw < H) {
        const float* wrow = comb_W + (long long)gw * 2 * H;
        float4 a[8];
        float acc = 0.f;
#pragma unroll
        for (int k = 0; k < 8; k++) a[k] = __ldcs((const float4*)(wrow + k * 128 + lane * 4));
#pragma unroll
        for (int k = 0; k < 8; k++) acc += dot4(a[k], *(const float4*)(erow + k * 128 + lane * 4));
#pragma unroll
        for (int k = 0; k < 8; k++) a[k] = __ldcs((const float4*)(wrow + H + k * 128 + lane * 4));
#pragma unroll
        for (int k = 0; k < 8; k++) acc += dot4(a[k], *(const float4*)(g_with_attn + k * 128 + lane * 4));
        acc = warp_sum(acc);
        if (lane == 0) g_rnn_in[gw] = fmaxf(acc + comb_b[gw], 0.f);
    }
    gbar(2);

    // ---- P3: GRU. warp per output i; 3 gate dots sequentially (a[8] reused) ----
    if (gw < H) {
        int i = gw;
        float gs[3];
#pragma unroll
        for (int g = 0; g < 3; g++) {
            const float* row = W_ih + (long long)(g * H + i) * H;
            float4 a[8];
#pragma unroll
            for (int k = 0; k < 8; k++) a[k] = __ldcs((const float4*)(row + k * 128 + lane * 4));
            float acc = 0.f;
#pragma unroll
            for (int k = 0; k < 8; k++) acc += dot4(a[k], *(const float4*)(g_rnn_in + k * 128 + lane * 4));
            gs[g] = warp_sum(acc);
        }
        if (lane == 0) {
            float gx_r = gs[0] + b_ih[i];
            float gx_z = gs[1] + b_ih[H + i];
            float gx_n = gs[2] + b_ih[2 * H + i];
            float r = 1.f / (1.f + expf(-(gx_r + g_gh[i])));
            float z = 1.f / (1.f + expf(-(gx_z + g_gh[H + i])));
            float n = tanhf(gx_n + r * g_gh[2 * H + i]);
            float h = (1.f - z) * n + z * hidden[i];
            g_hnew[i] = h;
            out[V + i] = h;
        }
    }
}

// ===== K2: big vocab GEMV (round-3 proven shape, unchanged) =====
__global__ void __launch_bounds__(256, 2) k_logits(const float* __restrict__ out_W,
                                                   const float* __restrict__ out_b) {
    int lane = threadIdx.x & 31;
    int warp = (blockIdx.x * blockDim.x + threadIdx.x) >> 5;
    int nwarps = (gridDim.x * blockDim.x) >> 5;
    float4 h[8];
#pragma unroll
    for (int k = 0; k < 8; k++)
        h[k] = *(const float4*)(g_hnew + k * 128 + lane * 4);
    float lmax = -INFINITY;
    for (int v0 = warp * 2; v0 < V - 1; v0 += nwarps * 2) {
        const float* row0 = out_W + (long long)v0 * H + lane * 4;
        const float* row1 = row0 + H;
        float4 a0[8], a1[8];
#pragma unroll
        for (int k = 0; k < 8; k++) a0[k] = __ldcs((const float4*)(row0 + k * 128));
#pragma unroll
        for (int k = 0; k < 8; k++) a1[k] = __ldcs((const float4*)(row1 + k * 128));
        float acc0 = 0.f, acc1 = 0.f;
#pragma unroll
        for (int k = 0; k < 8; k++) {
            acc0 += dot4(a0[k], h[k]);
            acc1 += dot4(a1[k], h[k]);
        }
        acc0 = warp_sum(acc0);
        acc1 = warp_sum(acc1);
        if (lane == 0) {
            float lg0 = acc0 + out_b[v0];
            float lg1 = acc1 + out_b[v0 + 1];
            g_logits[v0] = lg0;
            g_logits[v0 + 1] = lg1;
            lmax = fmaxf(lmax, fmaxf(lg0, lg1));
        }
    }
    if (warp == 0) {
        int v = V - 1;
        const float* row = out_W + (long long)v * H + lane * 4;
        float acc = 0.f;
#pragma unroll
        for (int k = 0; k < 8; k++)
            acc += dot4(__ldcs((const float4*)(row + k * 128)), h[k]);
        acc = warp_sum(acc);
        if (lane == 0) {
            float lg = acc + out_b[v];
            g_logits[v] = lg;
            lmax = fmaxf(lmax, lg);
        }
    }
    if (lane == 0 && lmax > -INFINITY) {
        atomicMax(&g_max_enc, enc_f(lmax));
    }
}

// ===== K3: sum of exp(logit - max) =====
__global__ void __launch_bounds__(256) k_sumexp() {
    float gmax = dec_f(g_max_enc);
    int idx = blockIdx.x * blockDim.x + threadIdx.x;
    int stride = gridDim.x * blockDim.x;
    float s = 0.f;
    for (int v = idx; v < V; v += stride) s += expf(g_logits[v] - gmax);
    s = warp_sum(s);
    __shared__ float red[8];
    if ((threadIdx.x & 31) == 0) red[threadIdx.x >> 5] = s;
    __syncthreads();
    if (threadIdx.x == 0) {
        float t = 0.f;
#pragma unroll
        for (int i = 0; i < 8; i++) t += red[i];
        atomicAdd(&g_sumexp, t);
    }
}

// ===== K4: logp[v] = logit[v] - (max + log(sumexp)) =====
__global__ void __launch_bounds__(256) k_writeout(float* __restrict__ out) {
    float gmax = dec_f(g_max_enc);
    float lse = gmax + logf(g_sumexp);
    int idx = blockIdx.x * blockDim.x + threadIdx.x;
    int stride = gridDim.x * blockDim.x;
    for (int v = idx; v < V; v += stride) out[v] = g_logits[v] - lse;
}

extern "C" void kernel_launch(void* const* d_in, const int* in_sizes, int n_in,
                              void* d_out, int out_size) {
    const int*   x       = (const int*)d_in[0];
    const float* hidden  = (const float*)d_in[1];
    const float* enc     = (const float*)d_in[2];
    const float* emb     = (const float*)d_in[3];
    const float* attn_W  = (const float*)d_in[4];
    const float* attn_b  = (const float*)d_in[5];
    const float* comb_W  = (const float*)d_in[6];
    const float* comb_b  = (const float*)d_in[7];
    const float* W_ih    = (const float*)d_in[8];
    const float* W_hh    = (const float*)d_in[9];
    const float* b_ih    = (const float*)d_in[10];
    const float* b_hh    = (const float*)d_in[11];
    const float* out_W   = (const float*)d_in[12];
    const float* out_b   = (const float*)d_in[13];
    float* out = (float*)d_out;   // layout: [logp V][h_new H][attn_w L]

    k_front<<<FNB, FNT>>>(x, hidden, enc, emb, attn_W, attn_b, comb_W, comb_b,
                          W_ih, W_hh, b_ih, b_hh, out);
    k_logits<<<296, 256>>>(out_W, out_b);
    k_sumexp<<<256, 256>>>();
    k_writeout<<<256, 256>>>(out);
}